// round 12
// baseline (speedup 1.0000x reference)
#include <cuda_runtime.h>
#include <cuda_fp16.h>

#define B    4
#define LQ   512
#define LK   512
#define E    128
#define D    256
#define TL   8            // l-rows per score/context CTA
#define QT   32           // qq per stage tile
#define QBLK 128          // qq per score-CTA
#define NTA  (QBLK / QT)  // 4 tiles per score-CTA
#define NTHR 256
#define QPAD 68           // half2 row stride (272B): rows bank-shifted by 4
#define TILE_F4 (QT * (E / 2) / 4)   // float4 per q tile = 512

// Scratch (allocation-free rule: __device__ globals). Projections in half2.
__device__ __half2 g_qproj[B * LQ * (E / 2)];
__device__ __half2 g_kproj[B * LK * (E / 2)];
__device__ float   g_scores[B * LK * LQ];   // exp(score), pre-normalization

typedef unsigned long long ull;

__device__ __forceinline__ __half2 tanh_h2(__half2 x) {
    unsigned xu = *reinterpret_cast<unsigned*>(&x);
    unsigned r;
    asm("tanh.approx.f16x2 %0, %1;" : "=r"(r) : "r"(xu));
    return *reinterpret_cast<__half2*>(&r);
}
__device__ __forceinline__ __half2 u2h(unsigned x) {
    __half2 h; *reinterpret_cast<unsigned*>(&h) = x; return h;
}
__device__ __forceinline__ ull pk(float a, float b) {
    ull r; asm("mov.b64 %0, {%1, %2};" : "=l"(r) : "f"(a), "f"(b)); return r;
}
__device__ __forceinline__ float2 upk(ull v) {
    float2 r; asm("mov.b64 {%0, %1}, %2;" : "=f"(r.x), "=f"(r.y) : "l"(v)); return r;
}
__device__ __forceinline__ ull fmax2(ull a, ull b, ull c) {
    ull r; asm("fma.rn.f32x2 %0, %1, %2, %3;" : "=l"(r) : "l"(a), "l"(b), "l"(c)); return r;
}
__device__ __forceinline__ void cpasync16(void* smem_dst, const void* gsrc) {
    unsigned s = (unsigned)__cvta_generic_to_shared(smem_dst);
    asm volatile("cp.async.cg.shared.global [%0], [%1], 16;" :: "r"(s), "l"(gsrc));
}

// ---------------------------------------------------------------------------
// Projection: out[r][e] = sum_d X[r][d] * W[d][e]; f32 accumulate, half2 store.
// (unchanged from R11)
// ---------------------------------------------------------------------------
__global__ __launch_bounds__(NTHR) void proj_kernel(
    const float* __restrict__ query, const float* __restrict__ key,
    const float* __restrict__ Wc1,   const float* __restrict__ Wc2)
{
    const float* X; const float* W; __half2* O;
    if (blockIdx.y == 0) { X = query; W = Wc1; O = g_qproj; }
    else                 { X = key;   W = Wc2; O = g_kproj; }

    const int row0 = blockIdx.x * 8;
    const int tid  = threadIdx.x;
    const int ep   = tid & 63;           // e-pair 0..63 (E/2)
    const int rg   = tid >> 6;           // 0..3 -> rows 2rg, 2rg+1

    __shared__ float xs[8 * D];          // 8 KB
    const float4* xv = (const float4*)(X + (size_t)row0 * D);
    #pragma unroll
    for (int i = tid; i < 8 * D / 4; i += NTHR)
        ((float4*)xs)[i] = xv[i];
    __syncthreads();

    const float2* Wp  = (const float2*)W;          // [D][E/2]
    const float*  x0s = xs + (2 * rg + 0) * D;
    const float*  x1s = xs + (2 * rg + 1) * D;

    float2 w[8], wn[8];
    #pragma unroll
    for (int j = 0; j < 8; j++)                    // prologue: chunk 0
        w[j] = Wp[j * (E / 2) + ep];

    float2 a0 = make_float2(0.f, 0.f), a1 = a0;
    #pragma unroll 2
    for (int d0 = 0; d0 < D; d0 += 8) {
        if (d0 + 8 < D) {
            #pragma unroll
            for (int j = 0; j < 8; j++)            // prefetch chunk d0+8 (MLP 8)
                wn[j] = Wp[(d0 + 8 + j) * (E / 2) + ep];
        }
        #pragma unroll
        for (int j = 0; j < 8; j++) {              // compute chunk d0
            float x0 = x0s[d0 + j];                // warp-uniform LDS broadcast
            float x1 = x1s[d0 + j];
            a0.x += x0 * w[j].x; a0.y += x0 * w[j].y;
            a1.x += x1 * w[j].x; a1.y += x1 * w[j].y;
        }
        #pragma unroll
        for (int j = 0; j < 8; j++) w[j] = wn[j];
    }
    O[(size_t)(row0 + 2 * rg + 0) * (E / 2) + ep] = __floats2half2_rn(a0.x, a0.y);
    O[(size_t)(row0 + 2 * rg + 1) * (E / 2) + ep] = __floats2half2_rn(a1.x, a1.y);
}

// ---------------------------------------------------------------------------
// Score kernel: writes exp(score) -> g_scores (scores bounded by sum|vc| <~12,
// so no-max softmax is f32-safe). Half2 inner loop, cp.async double buffer.
// Grid (LQ/QBLK=4, LK/TL=64, B=4) = 1024 CTAs, 256 thr, occ 7.
// ---------------------------------------------------------------------------
__global__ __launch_bounds__(NTHR, 7) void score_kernel(
    const float* __restrict__ vc, float* __restrict__ sc_out)
{
    const int qblk = blockIdx.x;
    const int l0   = blockIdx.y * TL;
    const int b    = blockIdx.z;
    const int tid  = threadIdx.x;
    const int w    = tid >> 5;
    const int lane = tid & 31;

    __shared__ __align__(16) __half2 ks[TL][QPAD];       // 2.2 KB
    __shared__ __align__(16) __half2 vcs[E / 2];         // 256 B
    __shared__ __align__(16) __half2 qs[2][QT][QPAD];    // 17.4 KB double buffer

    for (int i = tid; i < TL * (E / 2); i += NTHR)
        ks[i >> 6][i & 63] = g_kproj[(size_t)(b * LK + l0 + (i >> 6)) * (E / 2) + (i & 63)];
    if (tid < E / 2)
        vcs[tid] = __floats2half2_rn(vc[2 * tid], vc[2 * tid + 1]);

    const float4* qbase = (const float4*)(g_qproj + ((size_t)b * LQ + qblk * QBLK) * (E / 2));

    #pragma unroll
    for (int j = 0; j < 2; j++) {
        int i = tid + j * NTHR;                  // 0..511
        cpasync16(&qs[0][i >> 4][(i & 15) * 4], qbase + i);
    }
    asm volatile("cp.async.commit_group;");

    const int lrow = lane >> 2;              // 0..7
    const int qrow = w * 4 + (lane & 3);     // 0..31 within tile
    float* orow = sc_out + (size_t)(b * LK + l0 + lrow) * LQ + qblk * QBLK + qrow;

    #pragma unroll 1
    for (int t = 0; t < NTA; t++) {
        __syncthreads();                     // prev reads of buf[(t+1)&1] done
        if (t + 1 < NTA) {
            const float4* src = qbase + (size_t)(t + 1) * TILE_F4;
            #pragma unroll
            for (int j = 0; j < 2; j++) {
                int i = tid + j * NTHR;
                cpasync16(&qs[(t + 1) & 1][i >> 4][(i & 15) * 4], src + i);
            }
            asm volatile("cp.async.commit_group;");
            asm volatile("cp.async.wait_group 1;");   // tile t landed
        } else {
            asm volatile("cp.async.wait_group 0;");
        }
        __syncthreads();                     // tile t visible

        const uint2* qp = (const uint2*)qs[t & 1][qrow];
        const uint2* kp = (const uint2*)ks[lrow];
        const uint2* vp = (const uint2*)vcs;

        float facc = 0.f;
        #pragma unroll 4
        for (int c = 0; c < E / 16; c++) {               // 8 chunks of 16 e
            __half2 acc01 = __float2half2_rn(0.f);
            __half2 acc23 = __float2half2_rn(0.f);
            #pragma unroll
            for (int u = 0; u < 4; u++) {
                const int e4 = c * 4 + u;
                uint2 q = qp[e4];                        // 1 phase (8-way dup)
                uint2 k = kp[e4];                        // 1 phase (4-way dup)
                uint2 v = vp[e4];                        // broadcast
                __half2 t01 = tanh_h2(__hadd2(u2h(q.x), u2h(k.x)));
                __half2 t23 = tanh_h2(__hadd2(u2h(q.y), u2h(k.y)));
                acc01 = __hfma2(u2h(v.x), t01, acc01);
                acc23 = __hfma2(u2h(v.y), t23, acc23);
            }
            float2 f01 = __half22float2(acc01);
            float2 f23 = __half22float2(acc23);
            facc += (f01.x + f01.y) + (f23.x + f23.y);
        }
        orow[t * QT] = __expf(facc);                      // exp(score), f32
    }
}

// ---------------------------------------------------------------------------
// Fused normalize + context. Grid (2 D-halves, LK/TL=64, B) = 512 CTAs, 256 thr.
// Normalize: warp w owns row l0+w; reads exp(s), sums (no max pass needed),
// scales, writes probs to ps and (dsl==0) att_out.
// GEMM: f32x2 FMA paired over qq: p pairs come packed free via LDS.64 of the
// ps row; v pairs packed once per 4-qq chunk shared by all 8 l-rows; packed
// accumulators (two qq-parity partials per d), lanes summed in epilogue.
// ---------------------------------------------------------------------------
__global__ __launch_bounds__(NTHR, 2) void context_kernel(
    const float* __restrict__ value, const float* __restrict__ scores,
    float* __restrict__ att_out, float* __restrict__ ctx_out)
{
    const int dsl = blockIdx.x;              // 0..1 : D-half
    const int l0  = blockIdx.y * TL;
    const int b   = blockIdx.z;
    const int tid = threadIdx.x;
    const int w   = tid >> 5;                // warp = l-row (norm) = qq block (gemm)
    const int lane = tid & 31;

    __shared__ float  ps[TL][LQ];            // 16 KB probabilities
    __shared__ float4 red[TL][TL][32];       // 32 KB partials [qg][l][d4g]

    // ---- normalize (warp w owns row l0 + w): sum of exps, no max pass ----
    {
        const float4* srow = (const float4*)(scores + (size_t)(b * LK + l0 + w) * LQ);
        float4 v[4];
        float s = 0.f;
        #pragma unroll
        for (int k = 0; k < 4; k++) {
            v[k] = srow[lane + 32 * k];
            s += (v[k].x + v[k].y) + (v[k].z + v[k].w);
        }
        #pragma unroll
        for (int o = 16; o; o >>= 1) s += __shfl_xor_sync(0xffffffffu, s, o);
        const float inv = __fdividef(1.f, s);

        float4* prow = (float4*)ps[w];
        float4* arow = (float4*)(att_out + (size_t)(b * LK + l0 + w) * LQ);
        #pragma unroll
        for (int k = 0; k < 4; k++) {
            v[k].x *= inv; v[k].y *= inv; v[k].z *= inv; v[k].w *= inv;
            prow[lane + 32 * k] = v[k];          // conflict-free STS.128
            if (dsl == 0) arow[lane + 32 * k] = v[k];
        }
    }
    __syncthreads();

    // ---- context GEMM: D-half dsl, qq block w, f32x2 ----
    const float4* vbase = (const float4*)(value + (size_t)b * LQ * D) + dsl * 32 + lane;

    ull acc[TL][4];                          // [l][d-comp], packed qq-parity pairs
    #pragma unroll
    for (int l = 0; l < TL; l++)
        #pragma unroll
        for (int d = 0; d < 4; d++) acc[l][d] = pk(0.f, 0.f);

    const int q0 = w * 64;
    #pragma unroll 2
    for (int qc = 0; qc < 64; qc += 4) {
        const int qq = q0 + qc;
        float4 v0 = vbase[(qq + 0) * (D / 4)];
        float4 v1 = vbase[(qq + 1) * (D / 4)];
        float4 v2 = vbase[(qq + 2) * (D / 4)];
        float4 v3 = vbase[(qq + 3) * (D / 4)];
        ull vx01 = pk(v0.x, v1.x), vx23 = pk(v2.x, v3.x);
        ull vy01 = pk(v0.y, v1.y), vy23 = pk(v2.y, v3.y);
        ull vz01 = pk(v0.z, v1.z), vz23 = pk(v2.z, v3.z);
        ull vw01 = pk(v0.w, v1.w), vw23 = pk(v2.w, v3.w);
        #pragma unroll
        for (int l = 0; l < TL; l++) {
            ull p01 = *(const ull*)&ps[l][qq];       // LDS.64 broadcast (packed pair)
            ull p23 = *(const ull*)&ps[l][qq + 2];   // LDS.64 broadcast
            acc[l][0] = fmax2(p01, vx01, acc[l][0]);
            acc[l][0] = fmax2(p23, vx23, acc[l][0]);
            acc[l][1] = fmax2(p01, vy01, acc[l][1]);
            acc[l][1] = fmax2(p23, vy23, acc[l][1]);
            acc[l][2] = fmax2(p01, vz01, acc[l][2]);
            acc[l][2] = fmax2(p23, vz23, acc[l][2]);
            acc[l][3] = fmax2(p01, vw01, acc[l][3]);
            acc[l][3] = fmax2(p23, vw23, acc[l][3]);
        }
    }

    // epilogue: fold packed partials, write to red
    #pragma unroll
    for (int l = 0; l < TL; l++) {
        float2 fx = upk(acc[l][0]), fy = upk(acc[l][1]);
        float2 fz = upk(acc[l][2]), fw = upk(acc[l][3]);
        red[w][l][lane] = make_float4(fx.x + fx.y, fy.x + fy.y,
                                      fz.x + fz.y, fw.x + fw.y);
    }
    __syncthreads();

    float4 c = make_float4(0.f, 0.f, 0.f, 0.f);
    #pragma unroll
    for (int g = 0; g < TL; g++) {
        float4 r = red[g][w][lane];
        c.x += r.x; c.y += r.y; c.z += r.z; c.w += r.w;
    }
    ((float4*)ctx_out)[(size_t)(b * LK + l0 + w) * (D / 4) + dsl * 32 + lane] = c;
}

// ---------------------------------------------------------------------------
extern "C" void kernel_launch(void* const* d_in, const int* in_sizes, int n_in,
                              void* d_out, int out_size)
{
    const float* query = (const float*)d_in[0];
    const float* key   = (const float*)d_in[1];
    const float* value = (const float*)d_in[2];
    const float* Wc1   = (const float*)d_in[3];
    const float* Wc2   = (const float*)d_in[4];
    const float* vc    = (const float*)d_in[5];

    float* ctx = (float*)d_out;                 // [B, LK, D]
    float* att = ctx + (size_t)B * LK * D;      // [B, LK, LQ]

    float* sc;
    cudaGetSymbolAddress((void**)&sc, g_scores);

    proj_kernel<<<dim3(B * LQ / 8, 2), NTHR>>>(query, key, Wc1, Wc2);
    score_kernel<<<dim3(LQ / QBLK, LK / TL, B), NTHR>>>(vc, sc);
    context_kernel<<<dim3(2, LK / TL, B), NTHR>>>(value, sc, att, ctx);
}

// round 13
// speedup vs baseline: 1.0516x; 1.0516x over previous
#include <cuda_runtime.h>
#include <cuda_fp16.h>

#define B    4
#define LQ   512
#define LK   512
#define E    128
#define D    256
#define TL   8            // l-rows per score/context CTA
#define QT   32           // qq per stage tile
#define QBLK 128          // qq per score-CTA
#define NTA  (QBLK / QT)  // 4 tiles per score-CTA
#define NTHR 256
#define QPAD 68           // half2 row stride (272B): rows bank-shifted by 4
#define TILE_F4 (QT * (E / 2) / 4)   // float4 per q tile = 512

// Scratch (allocation-free rule: __device__ globals). Projections in half2.
__device__ __half2 g_qproj[B * LQ * (E / 2)];
__device__ __half2 g_kproj[B * LK * (E / 2)];
__device__ float   g_scores[B * LK * LQ];   // exp(score), pre-normalization

__device__ __forceinline__ __half2 tanh_h2(__half2 x) {
    unsigned xu = *reinterpret_cast<unsigned*>(&x);
    unsigned r;
    asm("tanh.approx.f16x2 %0, %1;" : "=r"(r) : "r"(xu));
    return *reinterpret_cast<__half2*>(&r);
}
__device__ __forceinline__ __half2 u2h(unsigned x) {
    __half2 h; *reinterpret_cast<unsigned*>(&h) = x; return h;
}
__device__ __forceinline__ void cpasync16(void* smem_dst, const void* gsrc) {
    unsigned s = (unsigned)__cvta_generic_to_shared(smem_dst);
    asm volatile("cp.async.cg.shared.global [%0], [%1], 16;" :: "r"(s), "l"(gsrc));
}

// ---------------------------------------------------------------------------
// Projection: out[r][e] = sum_d X[r][d] * W[d][e]; f32 accumulate, half2 store.
// (unchanged from R11)
// ---------------------------------------------------------------------------
__global__ __launch_bounds__(NTHR) void proj_kernel(
    const float* __restrict__ query, const float* __restrict__ key,
    const float* __restrict__ Wc1,   const float* __restrict__ Wc2)
{
    const float* X; const float* W; __half2* O;
    if (blockIdx.y == 0) { X = query; W = Wc1; O = g_qproj; }
    else                 { X = key;   W = Wc2; O = g_kproj; }

    const int row0 = blockIdx.x * 8;
    const int tid  = threadIdx.x;
    const int ep   = tid & 63;           // e-pair 0..63 (E/2)
    const int rg   = tid >> 6;           // 0..3 -> rows 2rg, 2rg+1

    __shared__ float xs[8 * D];          // 8 KB
    const float4* xv = (const float4*)(X + (size_t)row0 * D);
    #pragma unroll
    for (int i = tid; i < 8 * D / 4; i += NTHR)
        ((float4*)xs)[i] = xv[i];
    __syncthreads();

    const float2* Wp  = (const float2*)W;          // [D][E/2]
    const float*  x0s = xs + (2 * rg + 0) * D;
    const float*  x1s = xs + (2 * rg + 1) * D;

    float2 w[8], wn[8];
    #pragma unroll
    for (int j = 0; j < 8; j++)                    // prologue: chunk 0
        w[j] = Wp[j * (E / 2) + ep];

    float2 a0 = make_float2(0.f, 0.f), a1 = a0;
    #pragma unroll 2
    for (int d0 = 0; d0 < D; d0 += 8) {
        if (d0 + 8 < D) {
            #pragma unroll
            for (int j = 0; j < 8; j++)            // prefetch chunk d0+8 (MLP 8)
                wn[j] = Wp[(d0 + 8 + j) * (E / 2) + ep];
        }
        #pragma unroll
        for (int j = 0; j < 8; j++) {              // compute chunk d0
            float x0 = x0s[d0 + j];                // warp-uniform LDS broadcast
            float x1 = x1s[d0 + j];
            a0.x += x0 * w[j].x; a0.y += x0 * w[j].y;
            a1.x += x1 * w[j].x; a1.y += x1 * w[j].y;
        }
        #pragma unroll
        for (int j = 0; j < 8; j++) w[j] = wn[j];
    }
    O[(size_t)(row0 + 2 * rg + 0) * (E / 2) + ep] = __floats2half2_rn(a0.x, a0.y);
    O[(size_t)(row0 + 2 * rg + 1) * (E / 2) + ep] = __floats2half2_rn(a1.x, a1.y);
}

// ---------------------------------------------------------------------------
// Score kernel: writes exp(score) -> g_scores (scores bounded by sum|vc| <~12,
// so no-max softmax is f32-safe; verified R12 rel_err 3.99e-4).
// Grid (LQ/QBLK=4, LK/TL=64, B=4) = 1024 CTAs, 256 thr, occ 7.
// ---------------------------------------------------------------------------
__global__ __launch_bounds__(NTHR, 7) void score_kernel(
    const float* __restrict__ vc, float* __restrict__ sc_out)
{
    const int qblk = blockIdx.x;
    const int l0   = blockIdx.y * TL;
    const int b    = blockIdx.z;
    const int tid  = threadIdx.x;
    const int w    = tid >> 5;
    const int lane = tid & 31;

    __shared__ __align__(16) __half2 ks[TL][QPAD];       // 2.2 KB
    __shared__ __align__(16) __half2 vcs[E / 2];         // 256 B
    __shared__ __align__(16) __half2 qs[2][QT][QPAD];    // 17.4 KB double buffer

    for (int i = tid; i < TL * (E / 2); i += NTHR)
        ks[i >> 6][i & 63] = g_kproj[(size_t)(b * LK + l0 + (i >> 6)) * (E / 2) + (i & 63)];
    if (tid < E / 2)
        vcs[tid] = __floats2half2_rn(vc[2 * tid], vc[2 * tid + 1]);

    const float4* qbase = (const float4*)(g_qproj + ((size_t)b * LQ + qblk * QBLK) * (E / 2));

    #pragma unroll
    for (int j = 0; j < 2; j++) {
        int i = tid + j * NTHR;                  // 0..511
        cpasync16(&qs[0][i >> 4][(i & 15) * 4], qbase + i);
    }
    asm volatile("cp.async.commit_group;");

    const int lrow = lane >> 2;              // 0..7
    const int qrow = w * 4 + (lane & 3);     // 0..31 within tile
    float* orow = sc_out + (size_t)(b * LK + l0 + lrow) * LQ + qblk * QBLK + qrow;

    #pragma unroll 1
    for (int t = 0; t < NTA; t++) {
        __syncthreads();                     // prev reads of buf[(t+1)&1] done
        if (t + 1 < NTA) {
            const float4* src = qbase + (size_t)(t + 1) * TILE_F4;
            #pragma unroll
            for (int j = 0; j < 2; j++) {
                int i = tid + j * NTHR;
                cpasync16(&qs[(t + 1) & 1][i >> 4][(i & 15) * 4], src + i);
            }
            asm volatile("cp.async.commit_group;");
            asm volatile("cp.async.wait_group 1;");   // tile t landed
        } else {
            asm volatile("cp.async.wait_group 0;");
        }
        __syncthreads();                     // tile t visible

        const uint2* qp = (const uint2*)qs[t & 1][qrow];
        const uint2* kp = (const uint2*)ks[lrow];
        const uint2* vp = (const uint2*)vcs;

        float facc = 0.f;
        #pragma unroll 4
        for (int c = 0; c < E / 16; c++) {               // 8 chunks of 16 e
            __half2 acc01 = __float2half2_rn(0.f);
            __half2 acc23 = __float2half2_rn(0.f);
            #pragma unroll
            for (int u = 0; u < 4; u++) {
                const int e4 = c * 4 + u;
                uint2 q = qp[e4];                        // 1 phase (8-way dup)
                uint2 k = kp[e4];                        // 1 phase (4-way dup)
                uint2 v = vp[e4];                        // broadcast
                __half2 t01 = tanh_h2(__hadd2(u2h(q.x), u2h(k.x)));
                __half2 t23 = tanh_h2(__hadd2(u2h(q.y), u2h(k.y)));
                acc01 = __hfma2(u2h(v.x), t01, acc01);
                acc23 = __hfma2(u2h(v.y), t23, acc23);
            }
            float2 f01 = __half22float2(acc01);
            float2 f23 = __half22float2(acc23);
            facc += (f01.x + f01.y) + (f23.x + f23.y);
        }
        orow[t * QT] = __expf(facc);                      // exp(score), f32
    }
}

// ---------------------------------------------------------------------------
// Fused normalize + context. Grid (2 D-halves, LK/TL=64, B) = 512 CTAs, 256 thr.
// Normalize: no-max (exp already applied); sum + scale only.
// GEMM: R11's scalar-FFMA register tiling (measured good; f32x2 variants
// regressed twice -> banned here).
// ---------------------------------------------------------------------------
__global__ __launch_bounds__(NTHR, 4) void context_kernel(
    const float* __restrict__ value, const float* __restrict__ scores,
    float* __restrict__ att_out, float* __restrict__ ctx_out)
{
    const int dsl = blockIdx.x;              // 0..1 : D-half
    const int l0  = blockIdx.y * TL;
    const int b   = blockIdx.z;
    const int tid = threadIdx.x;
    const int w   = tid >> 5;                // warp = l-row (norm) = qq block (gemm)
    const int lane = tid & 31;

    __shared__ float  ps[TL][LQ];            // 16 KB probabilities
    __shared__ float4 red[TL][TL][32];       // 32 KB partials [qg][l][d4g]

    // ---- normalize (warp w owns row l0 + w): sum of exps, no max pass ----
    {
        const float4* srow = (const float4*)(scores + (size_t)(b * LK + l0 + w) * LQ);
        float4 v[4];
        float s = 0.f;
        #pragma unroll
        for (int k = 0; k < 4; k++) {
            v[k] = srow[lane + 32 * k];
            s += (v[k].x + v[k].y) + (v[k].z + v[k].w);
        }
        #pragma unroll
        for (int o = 16; o; o >>= 1) s += __shfl_xor_sync(0xffffffffu, s, o);
        const float inv = __fdividef(1.f, s);

        float4* prow = (float4*)ps[w];
        float4* arow = (float4*)(att_out + (size_t)(b * LK + l0 + w) * LQ);
        #pragma unroll
        for (int k = 0; k < 4; k++) {
            v[k].x *= inv; v[k].y *= inv; v[k].z *= inv; v[k].w *= inv;
            prow[lane + 32 * k] = v[k];          // conflict-free STS.128
            if (dsl == 0) arow[lane + 32 * k] = v[k];
        }
    }
    __syncthreads();

    // ---- context GEMM: D-half dsl, qq block w (scalar FFMA, R11 form) ----
    const float4* vbase = (const float4*)(value + (size_t)b * LQ * D) + dsl * 32 + lane;

    float4 acc[TL];
    #pragma unroll
    for (int l = 0; l < TL; l++) acc[l] = make_float4(0.f, 0.f, 0.f, 0.f);

    const int q0 = w * 64;
    #pragma unroll 2
    for (int qc = 0; qc < 64; qc += 4) {
        const int qq = q0 + qc;
        float4 v0 = vbase[(qq + 0) * (D / 4)];
        float4 v1 = vbase[(qq + 1) * (D / 4)];
        float4 v2 = vbase[(qq + 2) * (D / 4)];
        float4 v3 = vbase[(qq + 3) * (D / 4)];
        #pragma unroll
        for (int l = 0; l < TL; l++) {
            float4 p = *(const float4*)&ps[l][qq];   // broadcast LDS.128
            acc[l].x += p.x * v0.x; acc[l].y += p.x * v0.y;
            acc[l].z += p.x * v0.z; acc[l].w += p.x * v0.w;
            acc[l].x += p.y * v1.x; acc[l].y += p.y * v1.y;
            acc[l].z += p.y * v1.z; acc[l].w += p.y * v1.w;
            acc[l].x += p.z * v2.x; acc[l].y += p.z * v2.y;
            acc[l].z += p.z * v2.z; acc[l].w += p.z * v2.w;
            acc[l].x += p.w * v3.x; acc[l].y += p.w * v3.y;
            acc[l].z += p.w * v3.z; acc[l].w += p.w * v3.w;
        }
    }

    #pragma unroll
    for (int l = 0; l < TL; l++)
        red[w][l][lane] = acc[l];
    __syncthreads();

    float4 c = make_float4(0.f, 0.f, 0.f, 0.f);
    #pragma unroll
    for (int g = 0; g < TL; g++) {
        float4 r = red[g][w][lane];
        c.x += r.x; c.y += r.y; c.z += r.z; c.w += r.w;
    }
    ((float4*)ctx_out)[(size_t)(b * LK + l0 + w) * (D / 4) + dsl * 32 + lane] = c;
}

// ---------------------------------------------------------------------------
extern "C" void kernel_launch(void* const* d_in, const int* in_sizes, int n_in,
                              void* d_out, int out_size)
{
    const float* query = (const float*)d_in[0];
    const float* key   = (const float*)d_in[1];
    const float* value = (const float*)d_in[2];
    const float* Wc1   = (const float*)d_in[3];
    const float* Wc2   = (const float*)d_in[4];
    const float* vc    = (const float*)d_in[5];

    float* ctx = (float*)d_out;                 // [B, LK, D]
    float* att = ctx + (size_t)B * LK * D;      // [B, LK, LQ]

    float* sc;
    cudaGetSymbolAddress((void**)&sc, g_scores);

    proj_kernel<<<dim3(B * LQ / 8, 2), NTHR>>>(query, key, Wc1, Wc2);
    score_kernel<<<dim3(LQ / QBLK, LK / TL, B), NTHR>>>(vc, sc);
    context_kernel<<<dim3(2, LK / TL, B), NTHR>>>(value, sc, att, ctx);
}

// round 14
// speedup vs baseline: 1.1495x; 1.0931x over previous
#include <cuda_runtime.h>
#include <cuda_fp16.h>

#define B    4
#define LQ   512
#define LK   512
#define E    128
#define D    256
#define TL   8            // l-rows per score/context CTA
#define QT   32           // qq per stage tile
#define QBLK 128          // qq per score-CTA
#define NTA  (QBLK / QT)  // 4 tiles per score-CTA
#define NTHR 256
#define QPAD 68           // half2 row stride (272B): rows bank-shifted by 4
#define TILE_F4 (QT * (E / 2) / 4)   // float4 per q tile = 512

#define PSP  520          // ps_h row stride in halves (bank = 4r + c, conflict-free)
#define VSP  264          // vs_h row stride in halves (ldmatrix rows on disjoint bank quads)

// Scratch (allocation-free rule: __device__ globals). Projections in half2.
__device__ __half2 g_qproj[B * LQ * (E / 2)];
__device__ __half2 g_kproj[B * LK * (E / 2)];
__device__ float   g_scores[B * LK * LQ];   // exp(score), pre-normalization

__device__ __forceinline__ __half2 tanh_h2(__half2 x) {
    unsigned xu = *reinterpret_cast<unsigned*>(&x);
    unsigned r;
    asm("tanh.approx.f16x2 %0, %1;" : "=r"(r) : "r"(xu));
    return *reinterpret_cast<__half2*>(&r);
}
__device__ __forceinline__ __half2 u2h(unsigned x) {
    __half2 h; *reinterpret_cast<unsigned*>(&h) = x; return h;
}
__device__ __forceinline__ unsigned h2u(__half2 h) {
    return *reinterpret_cast<unsigned*>(&h);
}
__device__ __forceinline__ void cpasync16(void* smem_dst, const void* gsrc) {
    unsigned s = (unsigned)__cvta_generic_to_shared(smem_dst);
    asm volatile("cp.async.cg.shared.global [%0], [%1], 16;" :: "r"(s), "l"(gsrc));
}

// ---------------------------------------------------------------------------
// Projection (unchanged from R13, passing): f32 accumulate, half2 store.
// ---------------------------------------------------------------------------
__global__ __launch_bounds__(NTHR) void proj_kernel(
    const float* __restrict__ query, const float* __restrict__ key,
    const float* __restrict__ Wc1,   const float* __restrict__ Wc2)
{
    const float* X; const float* W; __half2* O;
    if (blockIdx.y == 0) { X = query; W = Wc1; O = g_qproj; }
    else                 { X = key;   W = Wc2; O = g_kproj; }

    const int row0 = blockIdx.x * 8;
    const int tid  = threadIdx.x;
    const int ep   = tid & 63;
    const int rg   = tid >> 6;

    __shared__ float xs[8 * D];
    const float4* xv = (const float4*)(X + (size_t)row0 * D);
    #pragma unroll
    for (int i = tid; i < 8 * D / 4; i += NTHR)
        ((float4*)xs)[i] = xv[i];
    __syncthreads();

    const float2* Wp  = (const float2*)W;
    const float*  x0s = xs + (2 * rg + 0) * D;
    const float*  x1s = xs + (2 * rg + 1) * D;

    float2 w[8], wn[8];
    #pragma unroll
    for (int j = 0; j < 8; j++)
        w[j] = Wp[j * (E / 2) + ep];

    float2 a0 = make_float2(0.f, 0.f), a1 = a0;
    #pragma unroll 2
    for (int d0 = 0; d0 < D; d0 += 8) {
        if (d0 + 8 < D) {
            #pragma unroll
            for (int j = 0; j < 8; j++)
                wn[j] = Wp[(d0 + 8 + j) * (E / 2) + ep];
        }
        #pragma unroll
        for (int j = 0; j < 8; j++) {
            float x0 = x0s[d0 + j];
            float x1 = x1s[d0 + j];
            a0.x += x0 * w[j].x; a0.y += x0 * w[j].y;
            a1.x += x1 * w[j].x; a1.y += x1 * w[j].y;
        }
        #pragma unroll
        for (int j = 0; j < 8; j++) w[j] = wn[j];
    }
    O[(size_t)(row0 + 2 * rg + 0) * (E / 2) + ep] = __floats2half2_rn(a0.x, a0.y);
    O[(size_t)(row0 + 2 * rg + 1) * (E / 2) + ep] = __floats2half2_rn(a1.x, a1.y);
}

// ---------------------------------------------------------------------------
// Score kernel (unchanged from R13, passing): exp(score) -> g_scores.
// ---------------------------------------------------------------------------
__global__ __launch_bounds__(NTHR, 7) void score_kernel(
    const float* __restrict__ vc, float* __restrict__ sc_out)
{
    const int qblk = blockIdx.x;
    const int l0   = blockIdx.y * TL;
    const int b    = blockIdx.z;
    const int tid  = threadIdx.x;
    const int w    = tid >> 5;
    const int lane = tid & 31;

    __shared__ __align__(16) __half2 ks[TL][QPAD];
    __shared__ __align__(16) __half2 vcs[E / 2];
    __shared__ __align__(16) __half2 qs[2][QT][QPAD];

    for (int i = tid; i < TL * (E / 2); i += NTHR)
        ks[i >> 6][i & 63] = g_kproj[(size_t)(b * LK + l0 + (i >> 6)) * (E / 2) + (i & 63)];
    if (tid < E / 2)
        vcs[tid] = __floats2half2_rn(vc[2 * tid], vc[2 * tid + 1]);

    const float4* qbase = (const float4*)(g_qproj + ((size_t)b * LQ + qblk * QBLK) * (E / 2));

    #pragma unroll
    for (int j = 0; j < 2; j++) {
        int i = tid + j * NTHR;
        cpasync16(&qs[0][i >> 4][(i & 15) * 4], qbase + i);
    }
    asm volatile("cp.async.commit_group;");

    const int lrow = lane >> 2;
    const int qrow = w * 4 + (lane & 3);
    float* orow = sc_out + (size_t)(b * LK + l0 + lrow) * LQ + qblk * QBLK + qrow;

    #pragma unroll 1
    for (int t = 0; t < NTA; t++) {
        __syncthreads();
        if (t + 1 < NTA) {
            const float4* src = qbase + (size_t)(t + 1) * TILE_F4;
            #pragma unroll
            for (int j = 0; j < 2; j++) {
                int i = tid + j * NTHR;
                cpasync16(&qs[(t + 1) & 1][i >> 4][(i & 15) * 4], src + i);
            }
            asm volatile("cp.async.commit_group;");
            asm volatile("cp.async.wait_group 1;");
        } else {
            asm volatile("cp.async.wait_group 0;");
        }
        __syncthreads();

        const uint2* qp = (const uint2*)qs[t & 1][qrow];
        const uint2* kp = (const uint2*)ks[lrow];
        const uint2* vp = (const uint2*)vcs;

        float facc = 0.f;
        #pragma unroll 4
        for (int c = 0; c < E / 16; c++) {
            __half2 acc01 = __float2half2_rn(0.f);
            __half2 acc23 = __float2half2_rn(0.f);
            #pragma unroll
            for (int u = 0; u < 4; u++) {
                const int e4 = c * 4 + u;
                uint2 q = qp[e4];
                uint2 k = kp[e4];
                uint2 v = vp[e4];
                __half2 t01 = tanh_h2(__hadd2(u2h(q.x), u2h(k.x)));
                __half2 t23 = tanh_h2(__hadd2(u2h(q.y), u2h(k.y)));
                acc01 = __hfma2(u2h(v.x), t01, acc01);
                acc23 = __hfma2(u2h(v.y), t23, acc23);
            }
            float2 f01 = __half22float2(acc01);
            float2 f23 = __half22float2(acc23);
            facc += (f01.x + f01.y) + (f23.x + f23.y);
        }
        orow[t * QT] = __expf(facc);
    }
}

// ---------------------------------------------------------------------------
// Fused normalize + tensor-core context.
// Grid (LK/TL=64, B) = 256 CTAs, 256 thr, full D per CTA.
// Normalize: warp w owns row l0+w; probs -> att_out (f32) AND ps_h (fp16).
// GEMM: m16n8k16 f16xf16+f32 mma. M=16 (rows 8-15 zero-padded), K=512 in
// 32-qq staged chunks (value f32 -> vs_h fp16), N=256 split 32 cols/warp.
// A frags: scalar LDS from ps_h (stride 520 halves: bank 4r+c, conflict-free).
// B frags: ldmatrix.x4.trans from vs_h (stride 264 halves: disjoint quads).
// C rows 0-7 (= c0,c1) written; rows 8-15 (c2,c3) discarded.
// ---------------------------------------------------------------------------
__global__ __launch_bounds__(NTHR, 4) void context_kernel(
    const float* __restrict__ value, const float* __restrict__ scores,
    float* __restrict__ att_out, float* __restrict__ ctx_out)
{
    const int l0   = blockIdx.x * TL;
    const int b    = blockIdx.y;
    const int tid  = threadIdx.x;
    const int w    = tid >> 5;
    const int lane = tid & 31;

    __shared__ __align__(16) __half ps_h[16][PSP];   // 16.6 KB (rows 8-15 zero)
    __shared__ __align__(16) __half vs_h[32][VSP];   // 16.9 KB value chunk

    // zero ps_h rows 8..15 (2080 uints)
    for (int i = tid; i < 8 * PSP / 2; i += NTHR)
        ((unsigned*)&ps_h[8][0])[i] = 0u;

    // ---- normalize (warp w owns row l0 + w): no-max softmax ----
    {
        const float4* srow = (const float4*)(scores + (size_t)(b * LK + l0 + w) * LQ);
        float4 v[4];
        float s = 0.f;
        #pragma unroll
        for (int k = 0; k < 4; k++) {
            v[k] = srow[lane + 32 * k];
            s += (v[k].x + v[k].y) + (v[k].z + v[k].w);
        }
        #pragma unroll
        for (int o = 16; o; o >>= 1) s += __shfl_xor_sync(0xffffffffu, s, o);
        const float inv = __fdividef(1.f, s);

        float4* arow = (float4*)(att_out + (size_t)(b * LK + l0 + w) * LQ);
        #pragma unroll
        for (int k = 0; k < 4; k++) {
            v[k].x *= inv; v[k].y *= inv; v[k].z *= inv; v[k].w *= inv;
            arow[lane + 32 * k] = v[k];                       // atten stays f32
            uint2 h;
            h.x = h2u(__floats2half2_rn(v[k].x, v[k].y));
            h.y = h2u(__floats2half2_rn(v[k].z, v[k].w));
            *(uint2*)&ps_h[w][(lane + 32 * k) * 4] = h;       // fp16 for mma
        }
    }
    __syncthreads();

    // ---- tensor-core GEMM ----
    const int n0  = w * 32;                   // warp's 32 d-cols (4 n8-tiles)
    const int r   = lane >> 2;                // A/C row 0..7
    const int cq  = lane & 3;                 // quad col
    const int grp = lane >> 3, rit = lane & 7;
    const int brow_off = (grp & 1) * 8 + rit;         // ldmatrix row within k16
    const int bcol_off = (grp >> 1) * 8;              // 0 or 8

    unsigned vs_base = (unsigned)__cvta_generic_to_shared(&vs_h[0][0]);

    float c[4][4];
    #pragma unroll
    for (int t = 0; t < 4; t++)
        #pragma unroll
        for (int i = 0; i < 4; i++) c[t][i] = 0.f;

    const float4* vsrc0 = (const float4*)(value + (size_t)b * LQ * D);

    #pragma unroll 1
    for (int ch = 0; ch < LQ / 32; ch++) {            // 16 chunks of 32 qq
        __syncthreads();                              // prev chunk reads done
        // stage 32x256 f32 -> fp16
        const float4* vsrc = vsrc0 + ch * 32 * (D / 4);
        #pragma unroll
        for (int j = 0; j < 8; j++) {
            int i = tid + j * NTHR;                   // 0..2047 float4
            int qq = i >> 6, d4 = i & 63;
            float4 fv = vsrc[i];
            uint2 h;
            h.x = h2u(__floats2half2_rn(fv.x, fv.y));
            h.y = h2u(__floats2half2_rn(fv.z, fv.w));
            *(uint2*)&vs_h[qq][d4 * 4] = h;
        }
        __syncthreads();

        #pragma unroll
        for (int ks = 0; ks < 2; ks++) {              // two k16 steps per chunk
            const int kabs = ch * 32 + ks * 16 + 2 * cq;   // absolute qq for A
            const int k0   = ks * 16;                      // local row for B
            unsigned a0 = *(const unsigned*)&ps_h[r    ][kabs    ];
            unsigned a1 = *(const unsigned*)&ps_h[r + 8][kabs    ];
            unsigned a2 = *(const unsigned*)&ps_h[r    ][kabs + 8];
            unsigned a3 = *(const unsigned*)&ps_h[r + 8][kabs + 8];

            #pragma unroll
            for (int p = 0; p < 2; p++) {             // n-tile pairs (n0+32p*? ) -> (0,8) and (16,24)
                unsigned addr = vs_base +
                    ((k0 + brow_off) * VSP + n0 + p * 16 + bcol_off) * 2;
                unsigned b0, b1, b2, b3;
                asm volatile(
                    "ldmatrix.sync.aligned.m8n8.x4.trans.shared.b16 {%0,%1,%2,%3}, [%4];"
                    : "=r"(b0), "=r"(b1), "=r"(b2), "=r"(b3) : "r"(addr));
                float* ca = c[2 * p];
                float* cb = c[2 * p + 1];
                asm volatile(
                    "mma.sync.aligned.m16n8k16.row.col.f32.f16.f16.f32 "
                    "{%0,%1,%2,%3}, {%4,%5,%6,%7}, {%8,%9}, {%0,%1,%2,%3};"
                    : "+f"(ca[0]), "+f"(ca[1]), "+f"(ca[2]), "+f"(ca[3])
                    : "r"(a0), "r"(a1), "r"(a2), "r"(a3), "r"(b0), "r"(b1));
                asm volatile(
                    "mma.sync.aligned.m16n8k16.row.col.f32.f16.f16.f32 "
                    "{%0,%1,%2,%3}, {%4,%5,%6,%7}, {%8,%9}, {%0,%1,%2,%3};"
                    : "+f"(cb[0]), "+f"(cb[1]), "+f"(cb[2]), "+f"(cb[3])
                    : "r"(a0), "r"(a1), "r"(a2), "r"(a3), "r"(b2), "r"(b3));
            }
        }
    }

    // ---- epilogue: rows 0-7 (c0,c1) only; rows 8-15 are padding ----
    float* crow = ctx_out + (size_t)(b * LK + l0 + r) * D;
    #pragma unroll
    for (int t = 0; t < 4; t++) {
        int n = n0 + t * 8 + 2 * cq;
        *(float2*)&crow[n] = make_float2(c[t][0], c[t][1]);
    }
}

// ---------------------------------------------------------------------------
extern "C" void kernel_launch(void* const* d_in, const int* in_sizes, int n_in,
                              void* d_out, int out_size)
{
    const float* query = (const float*)d_in[0];
    const float* key   = (const float*)d_in[1];
    const float* value = (const float*)d_in[2];
    const float* Wc1   = (const float*)d_in[3];
    const float* Wc2   = (const float*)d_in[4];
    const float* vc    = (const float*)d_in[5];

    float* ctx = (float*)d_out;                 // [B, LK, D]
    float* att = ctx + (size_t)B * LK * D;      // [B, LK, LQ]

    float* sc;
    cudaGetSymbolAddress((void**)&sc, g_scores);

    proj_kernel<<<dim3(B * LQ / 8, 2), NTHR>>>(query, key, Wc1, Wc2);
    score_kernel<<<dim3(LQ / QBLK, LK / TL, B), NTHR>>>(vc, sc);
    context_kernel<<<dim3(LK / TL, B), NTHR>>>(value, sc, att, ctx);
}

// round 15
// speedup vs baseline: 1.3122x; 1.1415x over previous
#include <cuda_runtime.h>
#include <cuda_fp16.h>

#define B    4
#define LQ   512
#define LK   512
#define E    128
#define D    256
#define TL   8            // l-rows per score/context CTA
#define QT   32           // qq per stage tile
#define QBLK 128          // qq per score-CTA
#define NTA  (QBLK / QT)  // 4 tiles per score-CTA
#define NTHR 256
#define QPAD 68           // half2 row stride (272B): rows bank-shifted by 4
#define TILE_F4 (QT * (E / 2) / 4)   // float4 per q tile = 512

#define PSP  520          // ps_h row stride in halves (bank = 4r + c, conflict-free)
#define VSP  264          // vs_h row stride in halves (ldmatrix rows on disjoint bank quads)

// proj mma tiling
#define PROWS 32          // rows per proj CTA
#define KC    64          // K chunk
#define XSP   72          // x_hi/x_lo row stride in halves (bank 4r+cq distinct)
#define WSP   136         // w_h row stride in halves (272B: ldmatrix rows on disjoint quads)

// Scratch (allocation-free rule: __device__ globals). Projections in half2.
__device__ __half2 g_qproj[B * LQ * (E / 2)];
__device__ __half2 g_kproj[B * LK * (E / 2)];
__device__ float   g_scores[B * LK * LQ];   // exp(score), pre-normalization

__device__ __forceinline__ __half2 tanh_h2(__half2 x) {
    unsigned xu = *reinterpret_cast<unsigned*>(&x);
    unsigned r;
    asm("tanh.approx.f16x2 %0, %1;" : "=r"(r) : "r"(xu));
    return *reinterpret_cast<__half2*>(&r);
}
__device__ __forceinline__ __half2 u2h(unsigned x) {
    __half2 h; *reinterpret_cast<unsigned*>(&h) = x; return h;
}
__device__ __forceinline__ unsigned h2u(__half2 h) {
    return *reinterpret_cast<unsigned*>(&h);
}
__device__ __forceinline__ void cpasync16(void* smem_dst, const void* gsrc) {
    unsigned s = (unsigned)__cvta_generic_to_shared(smem_dst);
    asm volatile("cp.async.cg.shared.global [%0], [%1], 16;" :: "r"(s), "l"(gsrc));
}

// ---------------------------------------------------------------------------
// Tensor-core projection: O[r][e] = sum_d X[r][d] * W[d][e], half2 output.
// Grid (2048/PROWS = 64, 2 sides) = 128 CTAs, 256 thr (8 warps).
// Warp (mt = w>>2, nt = w&3): tile rows mt*16..+15, cols nt*32..+31.
// Split-X two-pass mma: X = x_hi + x_lo (both fp16), W fp16, f32 accumulate
// -> X effectively exact; only W fp16 rounding remains (~5e-4 on products).
// K staged in 4 chunks of 64 (X 32x64, W 64x128, f32->fp16 at staging).
// ---------------------------------------------------------------------------
__global__ __launch_bounds__(NTHR, 4) void proj_kernel(
    const float* __restrict__ query, const float* __restrict__ key,
    const float* __restrict__ Wc1,   const float* __restrict__ Wc2)
{
    const float* X; const float* W; __half2* O;
    if (blockIdx.y == 0) { X = query; W = Wc1; O = g_qproj; }
    else                 { X = key;   W = Wc2; O = g_kproj; }

    const int row0 = blockIdx.x * PROWS;
    const int tid  = threadIdx.x;
    const int w    = tid >> 5;
    const int lane = tid & 31;

    __shared__ __align__(16) __half xhi[PROWS][XSP];  // 4.6 KB
    __shared__ __align__(16) __half xlo[PROWS][XSP];  // 4.6 KB
    __shared__ __align__(16) __half w_h[KC][WSP];     // 17.4 KB

    const int mt = w >> 2;                   // 0..1
    const int nt = w & 3;                    // 0..3
    const int r  = lane >> 2;                // 0..7
    const int cq = lane & 3;                 // 0..3
    const int grp = lane >> 3, rit = lane & 7;
    const int brow_off = (grp & 1) * 8 + rit;
    const int bcol_off = (grp >> 1) * 8;

    unsigned w_base = (unsigned)__cvta_generic_to_shared(&w_h[0][0]);

    float c[4][4];
    #pragma unroll
    for (int t = 0; t < 4; t++)
        #pragma unroll
        for (int i = 0; i < 4; i++) c[t][i] = 0.f;

    #pragma unroll 1
    for (int kc = 0; kc < D; kc += KC) {
        __syncthreads();                              // prev chunk reads done

        // stage X chunk [PROWS x KC] -> xhi + xlo (512 float4, 2/thread)
        #pragma unroll
        for (int j = 0; j < 2; j++) {
            int i = tid + j * NTHR;                   // 0..511
            int row = i >> 4, kf4 = (i & 15) * 4;
            float4 xv = *(const float4*)(X + (size_t)(row0 + row) * D + kc + kf4);
            __half h0 = __float2half_rn(xv.x), h1 = __float2half_rn(xv.y);
            __half h2 = __float2half_rn(xv.z), h3 = __float2half_rn(xv.w);
            uint2 hh;
            hh.x = h2u(__halves2half2(h0, h1));
            hh.y = h2u(__halves2half2(h2, h3));
            *(uint2*)&xhi[row][kf4] = hh;
            uint2 ll;
            ll.x = h2u(__floats2half2_rn(xv.x - __half2float(h0),
                                         xv.y - __half2float(h1)));
            ll.y = h2u(__floats2half2_rn(xv.z - __half2float(h2),
                                         xv.w - __half2float(h3)));
            *(uint2*)&xlo[row][kf4] = ll;
        }
        // stage W chunk [KC x E] -> fp16 (2048 float4, 8/thread)
        #pragma unroll
        for (int j = 0; j < 8; j++) {
            int i = tid + j * NTHR;                   // 0..2047
            int k = i >> 5, nf4 = (i & 31) * 4;
            float4 wv = *(const float4*)(W + (size_t)(kc + k) * E + nf4);
            uint2 hh;
            hh.x = h2u(__floats2half2_rn(wv.x, wv.y));
            hh.y = h2u(__floats2half2_rn(wv.z, wv.w));
            *(uint2*)&w_h[k][nf4] = hh;
        }
        __syncthreads();

        #pragma unroll
        for (int ks = 0; ks < KC / 16; ks++) {        // 4 k16 steps
            const int k16 = ks * 16;
            const int ar0 = mt * 16 + r, ar1 = mt * 16 + r + 8;
            unsigned ah0 = *(const unsigned*)&xhi[ar0][k16 + 2 * cq];
            unsigned ah1 = *(const unsigned*)&xhi[ar1][k16 + 2 * cq];
            unsigned ah2 = *(const unsigned*)&xhi[ar0][k16 + 2 * cq + 8];
            unsigned ah3 = *(const unsigned*)&xhi[ar1][k16 + 2 * cq + 8];
            unsigned al0 = *(const unsigned*)&xlo[ar0][k16 + 2 * cq];
            unsigned al1 = *(const unsigned*)&xlo[ar1][k16 + 2 * cq];
            unsigned al2 = *(const unsigned*)&xlo[ar0][k16 + 2 * cq + 8];
            unsigned al3 = *(const unsigned*)&xlo[ar1][k16 + 2 * cq + 8];

            #pragma unroll
            for (int p = 0; p < 2; p++) {
                unsigned addr = w_base +
                    ((k16 + brow_off) * WSP + nt * 32 + p * 16 + bcol_off) * 2;
                unsigned b0, b1, b2, b3;
                asm volatile(
                    "ldmatrix.sync.aligned.m8n8.x4.trans.shared.b16 {%0,%1,%2,%3}, [%4];"
                    : "=r"(b0), "=r"(b1), "=r"(b2), "=r"(b3) : "r"(addr));
                float* ca = c[2 * p];
                float* cb = c[2 * p + 1];
                asm volatile(
                    "mma.sync.aligned.m16n8k16.row.col.f32.f16.f16.f32 "
                    "{%0,%1,%2,%3}, {%4,%5,%6,%7}, {%8,%9}, {%0,%1,%2,%3};"
                    : "+f"(ca[0]), "+f"(ca[1]), "+f"(ca[2]), "+f"(ca[3])
                    : "r"(ah0), "r"(ah1), "r"(ah2), "r"(ah3), "r"(b0), "r"(b1));
                asm volatile(
                    "mma.sync.aligned.m16n8k16.row.col.f32.f16.f16.f32 "
                    "{%0,%1,%2,%3}, {%4,%5,%6,%7}, {%8,%9}, {%0,%1,%2,%3};"
                    : "+f"(ca[0]), "+f"(ca[1]), "+f"(ca[2]), "+f"(ca[3])
                    : "r"(al0), "r"(al1), "r"(al2), "r"(al3), "r"(b0), "r"(b1));
                asm volatile(
                    "mma.sync.aligned.m16n8k16.row.col.f32.f16.f16.f32 "
                    "{%0,%1,%2,%3}, {%4,%5,%6,%7}, {%8,%9}, {%0,%1,%2,%3};"
                    : "+f"(cb[0]), "+f"(cb[1]), "+f"(cb[2]), "+f"(cb[3])
                    : "r"(ah0), "r"(ah1), "r"(ah2), "r"(ah3), "r"(b2), "r"(b3));
                asm volatile(
                    "mma.sync.aligned.m16n8k16.row.col.f32.f16.f16.f32 "
                    "{%0,%1,%2,%3}, {%4,%5,%6,%7}, {%8,%9}, {%0,%1,%2,%3};"
                    : "+f"(cb[0]), "+f"(cb[1]), "+f"(cb[2]), "+f"(cb[3])
                    : "r"(al0), "r"(al1), "r"(al2), "r"(al3), "r"(b2), "r"(b3));
            }
        }
    }

    // epilogue: (c[t][0],c[t][1]) -> row mt*16+r; (c[t][2],c[t][3]) -> +8.
    // cols nt*32 + t*8 + 2cq (even) -> one half2 store each.
    #pragma unroll
    for (int t = 0; t < 4; t++) {
        int n = nt * 32 + t * 8 + 2 * cq;
        O[(size_t)(row0 + mt * 16 + r    ) * (E / 2) + n / 2] =
            __floats2half2_rn(c[t][0], c[t][1]);
        O[(size_t)(row0 + mt * 16 + r + 8) * (E / 2) + n / 2] =
            __floats2half2_rn(c[t][2], c[t][3]);
    }
}

// ---------------------------------------------------------------------------
// Score kernel (unchanged from R14, passing): exp(score) -> g_scores.
// ---------------------------------------------------------------------------
__global__ __launch_bounds__(NTHR, 7) void score_kernel(
    const float* __restrict__ vc, float* __restrict__ sc_out)
{
    const int qblk = blockIdx.x;
    const int l0   = blockIdx.y * TL;
    const int b    = blockIdx.z;
    const int tid  = threadIdx.x;
    const int w    = tid >> 5;
    const int lane = tid & 31;

    __shared__ __align__(16) __half2 ks[TL][QPAD];
    __shared__ __align__(16) __half2 vcs[E / 2];
    __shared__ __align__(16) __half2 qs[2][QT][QPAD];

    for (int i = tid; i < TL * (E / 2); i += NTHR)
        ks[i >> 6][i & 63] = g_kproj[(size_t)(b * LK + l0 + (i >> 6)) * (E / 2) + (i & 63)];
    if (tid < E / 2)
        vcs[tid] = __floats2half2_rn(vc[2 * tid], vc[2 * tid + 1]);

    const float4* qbase = (const float4*)(g_qproj + ((size_t)b * LQ + qblk * QBLK) * (E / 2));

    #pragma unroll
    for (int j = 0; j < 2; j++) {
        int i = tid + j * NTHR;
        cpasync16(&qs[0][i >> 4][(i & 15) * 4], qbase + i);
    }
    asm volatile("cp.async.commit_group;");

    const int lrow = lane >> 2;
    const int qrow = w * 4 + (lane & 3);
    float* orow = sc_out + (size_t)(b * LK + l0 + lrow) * LQ + qblk * QBLK + qrow;

    #pragma unroll 1
    for (int t = 0; t < NTA; t++) {
        __syncthreads();
        if (t + 1 < NTA) {
            const float4* src = qbase + (size_t)(t + 1) * TILE_F4;
            #pragma unroll
            for (int j = 0; j < 2; j++) {
                int i = tid + j * NTHR;
                cpasync16(&qs[(t + 1) & 1][i >> 4][(i & 15) * 4], src + i);
            }
            asm volatile("cp.async.commit_group;");
            asm volatile("cp.async.wait_group 1;");
        } else {
            asm volatile("cp.async.wait_group 0;");
        }
        __syncthreads();

        const uint2* qp = (const uint2*)qs[t & 1][qrow];
        const uint2* kp = (const uint2*)ks[lrow];
        const uint2* vp = (const uint2*)vcs;

        float facc = 0.f;
        #pragma unroll 4
        for (int c = 0; c < E / 16; c++) {
            __half2 acc01 = __float2half2_rn(0.f);
            __half2 acc23 = __float2half2_rn(0.f);
            #pragma unroll
            for (int u = 0; u < 4; u++) {
                const int e4 = c * 4 + u;
                uint2 q = qp[e4];
                uint2 k = kp[e4];
                uint2 v = vp[e4];
                __half2 t01 = tanh_h2(__hadd2(u2h(q.x), u2h(k.x)));
                __half2 t23 = tanh_h2(__hadd2(u2h(q.y), u2h(k.y)));
                acc01 = __hfma2(u2h(v.x), t01, acc01);
                acc23 = __hfma2(u2h(v.y), t23, acc23);
            }
            float2 f01 = __half22float2(acc01);
            float2 f23 = __half22float2(acc23);
            facc += (f01.x + f01.y) + (f23.x + f23.y);
        }
        orow[t * QT] = __expf(facc);
    }
}

// ---------------------------------------------------------------------------
// Fused normalize + tensor-core context (unchanged from R14, passing).
// ---------------------------------------------------------------------------
__global__ __launch_bounds__(NTHR, 4) void context_kernel(
    const float* __restrict__ value, const float* __restrict__ scores,
    float* __restrict__ att_out, float* __restrict__ ctx_out)
{
    const int l0   = blockIdx.x * TL;
    const int b    = blockIdx.y;
    const int tid  = threadIdx.x;
    const int w    = tid >> 5;
    const int lane = tid & 31;

    __shared__ __align__(16) __half ps_h[16][PSP];   // 16.6 KB (rows 8-15 zero)
    __shared__ __align__(16) __half vs_h[32][VSP];   // 16.9 KB value chunk

    for (int i = tid; i < 8 * PSP / 2; i += NTHR)
        ((unsigned*)&ps_h[8][0])[i] = 0u;

    // ---- normalize (warp w owns row l0 + w): no-max softmax ----
    {
        const float4* srow = (const float4*)(scores + (size_t)(b * LK + l0 + w) * LQ);
        float4 v[4];
        float s = 0.f;
        #pragma unroll
        for (int k = 0; k < 4; k++) {
            v[k] = srow[lane + 32 * k];
            s += (v[k].x + v[k].y) + (v[k].z + v[k].w);
        }
        #pragma unroll
        for (int o = 16; o; o >>= 1) s += __shfl_xor_sync(0xffffffffu, s, o);
        const float inv = __fdividef(1.f, s);

        float4* arow = (float4*)(att_out + (size_t)(b * LK + l0 + w) * LQ);
        #pragma unroll
        for (int k = 0; k < 4; k++) {
            v[k].x *= inv; v[k].y *= inv; v[k].z *= inv; v[k].w *= inv;
            arow[lane + 32 * k] = v[k];                       // atten stays f32
            uint2 h;
            h.x = h2u(__floats2half2_rn(v[k].x, v[k].y));
            h.y = h2u(__floats2half2_rn(v[k].z, v[k].w));
            *(uint2*)&ps_h[w][(lane + 32 * k) * 4] = h;       // fp16 for mma
        }
    }
    __syncthreads();

    const int n0  = w * 32;
    const int r   = lane >> 2;
    const int cq  = lane & 3;
    const int grp = lane >> 3, rit = lane & 7;
    const int brow_off = (grp & 1) * 8 + rit;
    const int bcol_off = (grp >> 1) * 8;

    unsigned vs_base = (unsigned)__cvta_generic_to_shared(&vs_h[0][0]);

    float c[4][4];
    #pragma unroll
    for (int t = 0; t < 4; t++)
        #pragma unroll
        for (int i = 0; i < 4; i++) c[t][i] = 0.f;

    const float4* vsrc0 = (const float4*)(value + (size_t)b * LQ * D);

    #pragma unroll 1
    for (int ch = 0; ch < LQ / 32; ch++) {
        __syncthreads();
        const float4* vsrc = vsrc0 + ch * 32 * (D / 4);
        #pragma unroll
        for (int j = 0; j < 8; j++) {
            int i = tid + j * NTHR;
            int qq = i >> 6, d4 = i & 63;
            float4 fv = vsrc[i];
            uint2 h;
            h.x = h2u(__floats2half2_rn(fv.x, fv.y));
            h.y = h2u(__floats2half2_rn(fv.z, fv.w));
            *(uint2*)&vs_h[qq][d4 * 4] = h;
        }
        __syncthreads();

        #pragma unroll
        for (int ks = 0; ks < 2; ks++) {
            const int kabs = ch * 32 + ks * 16 + 2 * cq;
            const int k0   = ks * 16;
            unsigned a0 = *(const unsigned*)&ps_h[r    ][kabs    ];
            unsigned a1 = *(const unsigned*)&ps_h[r + 8][kabs    ];
            unsigned a2 = *(const unsigned*)&ps_h[r    ][kabs + 8];
            unsigned a3 = *(const unsigned*)&ps_h[r + 8][kabs + 8];

            #pragma unroll
            for (int p = 0; p < 2; p++) {
                unsigned addr = vs_base +
                    ((k0 + brow_off) * VSP + n0 + p * 16 + bcol_off) * 2;
                unsigned b0, b1, b2, b3;
                asm volatile(
                    "ldmatrix.sync.aligned.m8n8.x4.trans.shared.b16 {%0,%1,%2,%3}, [%4];"
                    : "=r"(b0), "=r"(b1), "=r"(b2), "=r"(b3) : "r"(addr));
                float* ca = c[2 * p];
                float* cb = c[2 * p + 1];
                asm volatile(
                    "mma.sync.aligned.m16n8k16.row.col.f32.f16.f16.f32 "
                    "{%0,%1,%2,%3}, {%4,%5,%6,%7}, {%8,%9}, {%0,%1,%2,%3};"
                    : "+f"(ca[0]), "+f"(ca[1]), "+f"(ca[2]), "+f"(ca[3])
                    : "r"(a0), "r"(a1), "r"(a2), "r"(a3), "r"(b0), "r"(b1));
                asm volatile(
                    "mma.sync.aligned.m16n8k16.row.col.f32.f16.f16.f32 "
                    "{%0,%1,%2,%3}, {%4,%5,%6,%7}, {%8,%9}, {%0,%1,%2,%3};"
                    : "+f"(cb[0]), "+f"(cb[1]), "+f"(cb[2]), "+f"(cb[3])
                    : "r"(a0), "r"(a1), "r"(a2), "r"(a3), "r"(b2), "r"(b3));
            }
        }
    }

    float* crow = ctx_out + (size_t)(b * LK + l0 + r) * D;
    #pragma unroll
    for (int t = 0; t < 4; t++) {
        int n = n0 + t * 8 + 2 * cq;
        *(float2*)&crow[n] = make_float2(c[t][0], c[t][1]);
    }
}

// ---------------------------------------------------------------------------
extern "C" void kernel_launch(void* const* d_in, const int* in_sizes, int n_in,
                              void* d_out, int out_size)
{
    const float* query = (const float*)d_in[0];
    const float* key   = (const float*)d_in[1];
    const float* value = (const float*)d_in[2];
    const float* Wc1   = (const float*)d_in[3];
    const float* Wc2   = (const float*)d_in[4];
    const float* vc    = (const float*)d_in[5];

    float* ctx = (float*)d_out;                 // [B, LK, D]
    float* att = ctx + (size_t)B * LK * D;      // [B, LK, LQ]

    float* sc;
    cudaGetSymbolAddress((void**)&sc, g_scores);

    proj_kernel<<<dim3(2048 / PROWS, 2), NTHR>>>(query, key, Wc1, Wc2);
    score_kernel<<<dim3(LQ / QBLK, LK / TL, B), NTHR>>>(vc, sc);
    context_kernel<<<dim3(LK / TL, B), NTHR>>>(value, sc, att, ctx);
}

// round 16
// speedup vs baseline: 1.3664x; 1.0413x over previous
#include <cuda_runtime.h>
#include <cuda_fp16.h>

#define B    4
#define LQ   512
#define LK   512
#define E    128
#define D    256
#define TL   8            // l-rows per score/context CTA
#define QT   32           // qq per stage tile
#define QBLK 128          // qq per score-CTA
#define NTA  (QBLK / QT)  // 4 tiles per score-CTA
#define NTHR 256
#define QPAD 68           // half2 row stride (272B): rows bank-shifted by 4
#define TILE_F4 (QT * (E / 2) / 4)   // float4 per q tile = 512

#define PSP  520          // ps_h row stride in halves (bank = 4r + c, conflict-free)
#define VSP  264          // vs_h row stride in halves (ldmatrix rows on disjoint bank quads)

// proj mma tiling
#define PROWS 16          // rows per proj CTA -> 256 CTAs (was 128: SMs idle)
#define KC    64          // K chunk
#define XSP   72          // x_hi/x_lo row stride in halves (bank 4r+cq distinct)
#define WSP   136         // w_h row stride in halves (272B: ldmatrix rows on disjoint quads)

// Scratch (allocation-free rule: __device__ globals). Projections in half2.
__device__ __half2 g_qproj[B * LQ * (E / 2)];
__device__ __half2 g_kproj[B * LK * (E / 2)];
__device__ float   g_scores[B * LK * LQ];   // exp(score), pre-normalization

__device__ __forceinline__ __half2 tanh_h2(__half2 x) {
    unsigned xu = *reinterpret_cast<unsigned*>(&x);
    unsigned r;
    asm("tanh.approx.f16x2 %0, %1;" : "=r"(r) : "r"(xu));
    return *reinterpret_cast<__half2*>(&r);
}
__device__ __forceinline__ __half2 u2h(unsigned x) {
    __half2 h; *reinterpret_cast<unsigned*>(&h) = x; return h;
}
__device__ __forceinline__ unsigned h2u(__half2 h) {
    return *reinterpret_cast<unsigned*>(&h);
}
__device__ __forceinline__ void cpasync16(void* smem_dst, const void* gsrc) {
    unsigned s = (unsigned)__cvta_generic_to_shared(smem_dst);
    asm volatile("cp.async.cg.shared.global [%0], [%1], 16;" :: "r"(s), "l"(gsrc));
}

// ---------------------------------------------------------------------------
// Tensor-core projection: O[r][e] = sum_d X[r][d] * W[d][e], half2 output.
// Grid (2048/PROWS = 128, 2 sides) = 256 CTAs, 256 thr (8 warps).
// All warps share the single m16 row tile; warp w owns cols w*16..w*16+15
// (2 n8 tiles = one ldmatrix.x4 per k16 step).
// Split-X two-pass mma: X = x_hi + x_lo (both fp16), W fp16, f32 accumulate
// -> X effectively exact; only W fp16 rounding remains (~5e-4, verified R15).
// ---------------------------------------------------------------------------
__global__ __launch_bounds__(NTHR, 4) void proj_kernel(
    const float* __restrict__ query, const float* __restrict__ key,
    const float* __restrict__ Wc1,   const float* __restrict__ Wc2)
{
    const float* X; const float* W; __half2* O;
    if (blockIdx.y == 0) { X = query; W = Wc1; O = g_qproj; }
    else                 { X = key;   W = Wc2; O = g_kproj; }

    const int row0 = blockIdx.x * PROWS;
    const int tid  = threadIdx.x;
    const int w    = tid >> 5;
    const int lane = tid & 31;

    __shared__ __align__(16) __half xhi[PROWS][XSP];  // 2.3 KB
    __shared__ __align__(16) __half xlo[PROWS][XSP];  // 2.3 KB
    __shared__ __align__(16) __half w_h[KC][WSP];     // 17.4 KB

    const int n0 = w * 16;                   // warp's 16 cols
    const int r  = lane >> 2;                // 0..7
    const int cq = lane & 3;                 // 0..3
    const int grp = lane >> 3, rit = lane & 7;
    const int brow_off = (grp & 1) * 8 + rit;
    const int bcol_off = (grp >> 1) * 8;

    unsigned w_base = (unsigned)__cvta_generic_to_shared(&w_h[0][0]);

    float c[2][4];
    #pragma unroll
    for (int t = 0; t < 2; t++)
        #pragma unroll
        for (int i = 0; i < 4; i++) c[t][i] = 0.f;

    #pragma unroll 1
    for (int kc = 0; kc < D; kc += KC) {
        __syncthreads();                              // prev chunk reads done

        // stage X chunk [PROWS x KC] -> xhi + xlo (256 float4, 1/thread)
        {
            int i = tid;                              // 0..255
            int row = i >> 4, kf4 = (i & 15) * 4;
            float4 xv = *(const float4*)(X + (size_t)(row0 + row) * D + kc + kf4);
            __half h0 = __float2half_rn(xv.x), h1 = __float2half_rn(xv.y);
            __half h2 = __float2half_rn(xv.z), h3 = __float2half_rn(xv.w);
            uint2 hh;
            hh.x = h2u(__halves2half2(h0, h1));
            hh.y = h2u(__halves2half2(h2, h3));
            *(uint2*)&xhi[row][kf4] = hh;
            uint2 ll;
            ll.x = h2u(__floats2half2_rn(xv.x - __half2float(h0),
                                         xv.y - __half2float(h1)));
            ll.y = h2u(__floats2half2_rn(xv.z - __half2float(h2),
                                         xv.w - __half2float(h3)));
            *(uint2*)&xlo[row][kf4] = ll;
        }
        // stage W chunk [KC x E] -> fp16 (2048 float4, 8/thread)
        #pragma unroll
        for (int j = 0; j < 8; j++) {
            int i = tid + j * NTHR;                   // 0..2047
            int k = i >> 5, nf4 = (i & 31) * 4;
            float4 wv = *(const float4*)(W + (size_t)(kc + k) * E + nf4);
            uint2 hh;
            hh.x = h2u(__floats2half2_rn(wv.x, wv.y));
            hh.y = h2u(__floats2half2_rn(wv.z, wv.w));
            *(uint2*)&w_h[k][nf4] = hh;
        }
        __syncthreads();

        #pragma unroll
        for (int ks = 0; ks < KC / 16; ks++) {        // 4 k16 steps
            const int k16 = ks * 16;
            unsigned ah0 = *(const unsigned*)&xhi[r    ][k16 + 2 * cq];
            unsigned ah1 = *(const unsigned*)&xhi[r + 8][k16 + 2 * cq];
            unsigned ah2 = *(const unsigned*)&xhi[r    ][k16 + 2 * cq + 8];
            unsigned ah3 = *(const unsigned*)&xhi[r + 8][k16 + 2 * cq + 8];
            unsigned al0 = *(const unsigned*)&xlo[r    ][k16 + 2 * cq];
            unsigned al1 = *(const unsigned*)&xlo[r + 8][k16 + 2 * cq];
            unsigned al2 = *(const unsigned*)&xlo[r    ][k16 + 2 * cq + 8];
            unsigned al3 = *(const unsigned*)&xlo[r + 8][k16 + 2 * cq + 8];

            unsigned addr = w_base + ((k16 + brow_off) * WSP + n0 + bcol_off) * 2;
            unsigned b0, b1, b2, b3;
            asm volatile(
                "ldmatrix.sync.aligned.m8n8.x4.trans.shared.b16 {%0,%1,%2,%3}, [%4];"
                : "=r"(b0), "=r"(b1), "=r"(b2), "=r"(b3) : "r"(addr));
            asm volatile(
                "mma.sync.aligned.m16n8k16.row.col.f32.f16.f16.f32 "
                "{%0,%1,%2,%3}, {%4,%5,%6,%7}, {%8,%9}, {%0,%1,%2,%3};"
                : "+f"(c[0][0]), "+f"(c[0][1]), "+f"(c[0][2]), "+f"(c[0][3])
                : "r"(ah0), "r"(ah1), "r"(ah2), "r"(ah3), "r"(b0), "r"(b1));
            asm volatile(
                "mma.sync.aligned.m16n8k16.row.col.f32.f16.f16.f32 "
                "{%0,%1,%2,%3}, {%4,%5,%6,%7}, {%8,%9}, {%0,%1,%2,%3};"
                : "+f"(c[0][0]), "+f"(c[0][1]), "+f"(c[0][2]), "+f"(c[0][3])
                : "r"(al0), "r"(al1), "r"(al2), "r"(al3), "r"(b0), "r"(b1));
            asm volatile(
                "mma.sync.aligned.m16n8k16.row.col.f32.f16.f16.f32 "
                "{%0,%1,%2,%3}, {%4,%5,%6,%7}, {%8,%9}, {%0,%1,%2,%3};"
                : "+f"(c[1][0]), "+f"(c[1][1]), "+f"(c[1][2]), "+f"(c[1][3])
                : "r"(ah0), "r"(ah1), "r"(ah2), "r"(ah3), "r"(b2), "r"(b3));
            asm volatile(
                "mma.sync.aligned.m16n8k16.row.col.f32.f16.f16.f32 "
                "{%0,%1,%2,%3}, {%4,%5,%6,%7}, {%8,%9}, {%0,%1,%2,%3};"
                : "+f"(c[1][0]), "+f"(c[1][1]), "+f"(c[1][2]), "+f"(c[1][3])
                : "r"(al0), "r"(al1), "r"(al2), "r"(al3), "r"(b2), "r"(b3));
        }
    }

    // epilogue: rows r (c0,c1) and r+8 (c2,c3); cols n0 + t*8 + 2cq.
    #pragma unroll
    for (int t = 0; t < 2; t++) {
        int n = n0 + t * 8 + 2 * cq;
        O[(size_t)(row0 + r    ) * (E / 2) + n / 2] =
            __floats2half2_rn(c[t][0], c[t][1]);
        O[(size_t)(row0 + r + 8) * (E / 2) + n / 2] =
            __floats2half2_rn(c[t][2], c[t][3]);
    }
}

// ---------------------------------------------------------------------------
// Score kernel (unchanged, passing): exp(score) -> g_scores.
// ---------------------------------------------------------------------------
__global__ __launch_bounds__(NTHR, 7) void score_kernel(
    const float* __restrict__ vc, float* __restrict__ sc_out)
{
    const int qblk = blockIdx.x;
    const int l0   = blockIdx.y * TL;
    const int b    = blockIdx.z;
    const int tid  = threadIdx.x;
    const int w    = tid >> 5;
    const int lane = tid & 31;

    __shared__ __align__(16) __half2 ks[TL][QPAD];
    __shared__ __align__(16) __half2 vcs[E / 2];
    __shared__ __align__(16) __half2 qs[2][QT][QPAD];

    for (int i = tid; i < TL * (E / 2); i += NTHR)
        ks[i >> 6][i & 63] = g_kproj[(size_t)(b * LK + l0 + (i >> 6)) * (E / 2) + (i & 63)];
    if (tid < E / 2)
        vcs[tid] = __floats2half2_rn(vc[2 * tid], vc[2 * tid + 1]);

    const float4* qbase = (const float4*)(g_qproj + ((size_t)b * LQ + qblk * QBLK) * (E / 2));

    #pragma unroll
    for (int j = 0; j < 2; j++) {
        int i = tid + j * NTHR;
        cpasync16(&qs[0][i >> 4][(i & 15) * 4], qbase + i);
    }
    asm volatile("cp.async.commit_group;");

    const int lrow = lane >> 2;
    const int qrow = w * 4 + (lane & 3);
    float* orow = sc_out + (size_t)(b * LK + l0 + lrow) * LQ + qblk * QBLK + qrow;

    #pragma unroll 1
    for (int t = 0; t < NTA; t++) {
        __syncthreads();
        if (t + 1 < NTA) {
            const float4* src = qbase + (size_t)(t + 1) * TILE_F4;
            #pragma unroll
            for (int j = 0; j < 2; j++) {
                int i = tid + j * NTHR;
                cpasync16(&qs[(t + 1) & 1][i >> 4][(i & 15) * 4], src + i);
            }
            asm volatile("cp.async.commit_group;");
            asm volatile("cp.async.wait_group 1;");
        } else {
            asm volatile("cp.async.wait_group 0;");
        }
        __syncthreads();

        const uint2* qp = (const uint2*)qs[t & 1][qrow];
        const uint2* kp = (const uint2*)ks[lrow];
        const uint2* vp = (const uint2*)vcs;

        float facc = 0.f;
        #pragma unroll 4
        for (int c = 0; c < E / 16; c++) {
            __half2 acc01 = __float2half2_rn(0.f);
            __half2 acc23 = __float2half2_rn(0.f);
            #pragma unroll
            for (int u = 0; u < 4; u++) {
                const int e4 = c * 4 + u;
                uint2 q = qp[e4];
                uint2 k = kp[e4];
                uint2 v = vp[e4];
                __half2 t01 = tanh_h2(__hadd2(u2h(q.x), u2h(k.x)));
                __half2 t23 = tanh_h2(__hadd2(u2h(q.y), u2h(k.y)));
                acc01 = __hfma2(u2h(v.x), t01, acc01);
                acc23 = __hfma2(u2h(v.y), t23, acc23);
            }
            float2 f01 = __half22float2(acc01);
            float2 f23 = __half22float2(acc23);
            facc += (f01.x + f01.y) + (f23.x + f23.y);
        }
        orow[t * QT] = __expf(facc);
    }
}

// ---------------------------------------------------------------------------
// Fused normalize + tensor-core context (unchanged, passing).
// ---------------------------------------------------------------------------
__global__ __launch_bounds__(NTHR, 4) void context_kernel(
    const float* __restrict__ value, const float* __restrict__ scores,
    float* __restrict__ att_out, float* __restrict__ ctx_out)
{
    const int l0   = blockIdx.x * TL;
    const int b    = blockIdx.y;
    const int tid  = threadIdx.x;
    const int w    = tid >> 5;
    const int lane = tid & 31;

    __shared__ __align__(16) __half ps_h[16][PSP];   // 16.6 KB (rows 8-15 zero)
    __shared__ __align__(16) __half vs_h[32][VSP];   // 16.9 KB value chunk

    for (int i = tid; i < 8 * PSP / 2; i += NTHR)
        ((unsigned*)&ps_h[8][0])[i] = 0u;

    // ---- normalize (warp w owns row l0 + w): no-max softmax ----
    {
        const float4* srow = (const float4*)(scores + (size_t)(b * LK + l0 + w) * LQ);
        float4 v[4];
        float s = 0.f;
        #pragma unroll
        for (int k = 0; k < 4; k++) {
            v[k] = srow[lane + 32 * k];
            s += (v[k].x + v[k].y) + (v[k].z + v[k].w);
        }
        #pragma unroll
        for (int o = 16; o; o >>= 1) s += __shfl_xor_sync(0xffffffffu, s, o);
        const float inv = __fdividef(1.f, s);

        float4* arow = (float4*)(att_out + (size_t)(b * LK + l0 + w) * LQ);
        #pragma unroll
        for (int k = 0; k < 4; k++) {
            v[k].x *= inv; v[k].y *= inv; v[k].z *= inv; v[k].w *= inv;
            arow[lane + 32 * k] = v[k];                       // atten stays f32
            uint2 h;
            h.x = h2u(__floats2half2_rn(v[k].x, v[k].y));
            h.y = h2u(__floats2half2_rn(v[k].z, v[k].w));
            *(uint2*)&ps_h[w][(lane + 32 * k) * 4] = h;       // fp16 for mma
        }
    }
    __syncthreads();

    const int n0  = w * 32;
    const int r   = lane >> 2;
    const int cq  = lane & 3;
    const int grp = lane >> 3, rit = lane & 7;
    const int brow_off = (grp & 1) * 8 + rit;
    const int bcol_off = (grp >> 1) * 8;

    unsigned vs_base = (unsigned)__cvta_generic_to_shared(&vs_h[0][0]);

    float c[4][4];
    #pragma unroll
    for (int t = 0; t < 4; t++)
        #pragma unroll
        for (int i = 0; i < 4; i++) c[t][i] = 0.f;

    const float4* vsrc0 = (const float4*)(value + (size_t)b * LQ * D);

    #pragma unroll 1
    for (int ch = 0; ch < LQ / 32; ch++) {
        __syncthreads();
        const float4* vsrc = vsrc0 + ch * 32 * (D / 4);
        #pragma unroll
        for (int j = 0; j < 8; j++) {
            int i = tid + j * NTHR;
            int qq = i >> 6, d4 = i & 63;
            float4 fv = vsrc[i];
            uint2 h;
            h.x = h2u(__floats2half2_rn(fv.x, fv.y));
            h.y = h2u(__floats2half2_rn(fv.z, fv.w));
            *(uint2*)&vs_h[qq][d4 * 4] = h;
        }
        __syncthreads();

        #pragma unroll
        for (int ks = 0; ks < 2; ks++) {
            const int kabs = ch * 32 + ks * 16 + 2 * cq;
            const int k0   = ks * 16;
            unsigned a0 = *(const unsigned*)&ps_h[r    ][kabs    ];
            unsigned a1 = *(const unsigned*)&ps_h[r + 8][kabs    ];
            unsigned a2 = *(const unsigned*)&ps_h[r    ][kabs + 8];
            unsigned a3 = *(const unsigned*)&ps_h[r + 8][kabs + 8];

            #pragma unroll
            for (int p = 0; p < 2; p++) {
                unsigned addr = vs_base +
                    ((k0 + brow_off) * VSP + n0 + p * 16 + bcol_off) * 2;
                unsigned b0, b1, b2, b3;
                asm volatile(
                    "ldmatrix.sync.aligned.m8n8.x4.trans.shared.b16 {%0,%1,%2,%3}, [%4];"
                    : "=r"(b0), "=r"(b1), "=r"(b2), "=r"(b3) : "r"(addr));
                float* ca = c[2 * p];
                float* cb = c[2 * p + 1];
                asm volatile(
                    "mma.sync.aligned.m16n8k16.row.col.f32.f16.f16.f32 "
                    "{%0,%1,%2,%3}, {%4,%5,%6,%7}, {%8,%9}, {%0,%1,%2,%3};"
                    : "+f"(ca[0]), "+f"(ca[1]), "+f"(ca[2]), "+f"(ca[3])
                    : "r"(a0), "r"(a1), "r"(a2), "r"(a3), "r"(b0), "r"(b1));
                asm volatile(
                    "mma.sync.aligned.m16n8k16.row.col.f32.f16.f16.f32 "
                    "{%0,%1,%2,%3}, {%4,%5,%6,%7}, {%8,%9}, {%0,%1,%2,%3};"
                    : "+f"(cb[0]), "+f"(cb[1]), "+f"(cb[2]), "+f"(cb[3])
                    : "r"(a0), "r"(a1), "r"(a2), "r"(a3), "r"(b2), "r"(b3));
            }
        }
    }

    float* crow = ctx_out + (size_t)(b * LK + l0 + r) * D;
    #pragma unroll
    for (int t = 0; t < 4; t++) {
        int n = n0 + t * 8 + 2 * cq;
        *(float2*)&crow[n] = make_float2(c[t][0], c[t][1]);
    }
}

// ---------------------------------------------------------------------------
extern "C" void kernel_launch(void* const* d_in, const int* in_sizes, int n_in,
                              void* d_out, int out_size)
{
    const float* query = (const float*)d_in[0];
    const float* key   = (const float*)d_in[1];
    const float* value = (const float*)d_in[2];
    const float* Wc1   = (const float*)d_in[3];
    const float* Wc2   = (const float*)d_in[4];
    const float* vc    = (const float*)d_in[5];

    float* ctx = (float*)d_out;                 // [B, LK, D]
    float* att = ctx + (size_t)B * LK * D;      // [B, LK, LQ]

    float* sc;
    cudaGetSymbolAddress((void**)&sc, g_scores);

    proj_kernel<<<dim3(2048 / PROWS, 2), NTHR>>>(query, key, Wc1, Wc2);
    score_kernel<<<dim3(LQ / QBLK, LK / TL, B), NTHR>>>(vc, sc);
    context_kernel<<<dim3(LK / TL, B), NTHR>>>(value, sc, att, ctx);
}